// round 16
// baseline (speedup 1.0000x reference)
#include <cuda_runtime.h>
#include <cuda_bf16.h>
#include <math.h>
#include <stdint.h>

// Problem constants
#define BS 4096
#define HL 20
#define NF 128
#define EF 128
#define TF 128
#define DM 640          // 3*NF + EF + TF
#define DIN 512         // DM - TF
#define NHEAD 2
#define DH 320          // DM / NHEAD
#define ODE_STEPS 8

// K-block interleave (4x4 transpose within each 16-block; self-inverse).
#define PERM(k) (((k) & ~15) | (((k) & 3) << 2) | (((k) & 15) >> 2))

// ---------------- scratch (device globals; no allocation allowed) ----------
__device__ float g_full [(size_t)BS*HL*DM];     // full_vals (tf32, PERM space)
__device__ float g_nb   [(size_t)BS*HL*384];    // nb (tf32, PERM space)
__device__ float g_lef  [(size_t)BS*DIN];       // last_event_feat (tf32, PERM)
__device__ float g_u1v  [1280];                 // batch-independent u1 vector
__device__ float g_tqv  [640];                  // qlast vector (batch-indep)
__device__ float g_s    [(size_t)BS*1280];      // weighted sums (tf32, PERM)
__device__ float g_u2   [(size_t)BS*384];       // u2 (tf32, PERM)
__device__ float g_gi   [(size_t)BS*384];
__device__ float g_cat2 [(size_t)BS*512];       // [ss2|nf] (tf32, PERM)
__device__ float g_hpl  [(size_t)BS*NF];        // tanh-merge out (tf32, PERM)
__device__ float g_gh   [(size_t)BS*384];       // GRU hh gates (normal)
__device__ float g_odewT[NF*NF];
__device__ float g_gwih [384*512];              // tf32+PERM gru_w_ih
__device__ float g_gwhh2[384*128];              // tf32+PERM gru_w_hh
__device__ float g_wq2  [128*640];              // outfn_w @ out_proj_w (fp32)
__device__ float g_w3   [128*640];              // attn_wq^T outfn out_proj (fp32)
__device__ float g_bq2  [128];
__device__ float g_w4   [128*1280];             // W3 folded with Wv (tf32, K-PERM)
__device__ float g_b4   [128];
__device__ float g_w5   [384*1280];             // awk . W4 (tf32, K-PERM)
__device__ float g_b5   [384];                  // awk . b4
__device__ float g_wm2  [384*128];              // attn_wv @ merge_w_top (fp32)
__device__ float g_wcat [128*512];              // [Wm2; merge_w_bot]^T (tf32, K-PERM)

__device__ __forceinline__ uint32_t f2tf(float x) {
    uint32_t u; asm("cvt.rna.tf32.f32 %0, %1;" : "=r"(u) : "f"(x)); return u;
}
__device__ __forceinline__ float tfr(float x) { return __uint_as_float(f2tf(x)); }

__device__ __forceinline__ void cp16(uint32_t dst, const void* src) {
    asm volatile("cp.async.cg.shared.global [%0], [%1], 16;" :: "r"(dst), "l"(src));
}

// ---------------- TF32 mma.sync GEMM, TN form, K-interleaved operands -------
template<bool PERMOUT, bool TANH>
__global__ __launch_bounds__(256, 2)
void tgemm(int K, const float* __restrict__ A, int lda,
           const float* __restrict__ B,
           float* __restrict__ C, int ldc,
           const float* __restrict__ bias)
{
    __shared__ float As[3][128][16];
    __shared__ float Bs[3][128][16];
    int tid = threadIdx.x;
    int warp = tid >> 5, lane = tid & 31;
    int row0 = blockIdx.y * 128, col0 = blockIdx.x * 128;
    int m0 = (warp >> 1) * 32, n0 = (warp & 1) * 64;
    int g = lane >> 2, t = lane & 3;

    float c[2][8][4];
#pragma unroll
    for (int mi = 0; mi < 2; mi++)
#pragma unroll
        for (int ni = 0; ni < 8; ni++)
#pragma unroll
            for (int i = 0; i < 4; i++) c[mi][ni][i] = 0.f;

    const float* Ap = A + (size_t)row0 * lda;
    const float* Bp = B + (size_t)col0 * K;

    uint32_t sA = (uint32_t)__cvta_generic_to_shared(&As[0][0][0]);
    uint32_t sB = (uint32_t)__cvta_generic_to_shared(&Bs[0][0][0]);
    const uint32_t stg = 128u*16u*4u;

#define LOADSTAGE(s, kt) {                                                    \
        _Pragma("unroll")                                                     \
        for (int i = 0; i < 2; i++) {                                         \
            int j = tid + i*256, r = j >> 2, q = j & 3;                       \
            cp16(sA + (uint32_t)(s)*stg + (uint32_t)(r*16 + q*4)*4u,          \
                 Ap + (size_t)r*lda + (kt)*16 + q*4);                         \
            cp16(sB + (uint32_t)(s)*stg + (uint32_t)(r*16 + q*4)*4u,          \
                 Bp + (size_t)r*K + (kt)*16 + q*4);                           \
        }                                                                     \
        asm volatile("cp.async.commit_group;" ::: "memory");                  \
    }

    int T = K >> 4;
    LOADSTAGE(0, 0);
    LOADSTAGE(1, 1);

    int s = 0, sw = 2;
    for (int kt = 0; kt < T; kt++) {
        if (kt + 1 < T) asm volatile("cp.async.wait_group 1;" ::: "memory");
        else            asm volatile("cp.async.wait_group 0;" ::: "memory");
        __syncthreads();
        if (kt + 2 < T) LOADSTAGE(sw, kt + 2);

        float4 av[2][2], bv[8];
#pragma unroll
        for (int mi = 0; mi < 2; mi++) {
            int rm = m0 + mi*16 + g;
            av[mi][0] = *(const float4*)&As[s][rm    ][t*4];
            av[mi][1] = *(const float4*)&As[s][rm + 8][t*4];
        }
#pragma unroll
        for (int ni = 0; ni < 8; ni++) {
            int cn = n0 + ni*8 + g;
            bv[ni] = *(const float4*)&Bs[s][cn][t*4];
        }
#pragma unroll
        for (int mi = 0; mi < 2; mi++)
#pragma unroll
            for (int ni = 0; ni < 8; ni++) {
                asm volatile(
                    "mma.sync.aligned.m16n8k8.row.col.f32.tf32.tf32.f32 "
                    "{%0,%1,%2,%3},{%4,%5,%6,%7},{%8,%9},{%0,%1,%2,%3};\n"
                    : "+f"(c[mi][ni][0]), "+f"(c[mi][ni][1]),
                      "+f"(c[mi][ni][2]), "+f"(c[mi][ni][3])
                    : "r"(__float_as_uint(av[mi][0].x)), "r"(__float_as_uint(av[mi][1].x)),
                      "r"(__float_as_uint(av[mi][0].y)), "r"(__float_as_uint(av[mi][1].y)),
                      "r"(__float_as_uint(bv[ni].x)),    "r"(__float_as_uint(bv[ni].y)));
                asm volatile(
                    "mma.sync.aligned.m16n8k8.row.col.f32.tf32.tf32.f32 "
                    "{%0,%1,%2,%3},{%4,%5,%6,%7},{%8,%9},{%0,%1,%2,%3};\n"
                    : "+f"(c[mi][ni][0]), "+f"(c[mi][ni][1]),
                      "+f"(c[mi][ni][2]), "+f"(c[mi][ni][3])
                    : "r"(__float_as_uint(av[mi][0].z)), "r"(__float_as_uint(av[mi][1].z)),
                      "r"(__float_as_uint(av[mi][0].w)), "r"(__float_as_uint(av[mi][1].w)),
                      "r"(__float_as_uint(bv[ni].z)),    "r"(__float_as_uint(bv[ni].w)));
            }
        __syncthreads();
        s  = (s  == 2) ? 0 : s  + 1;
        sw = (sw == 2) ? 0 : sw + 1;
    }

#pragma unroll
    for (int mi = 0; mi < 2; mi++) {
        size_t r1 = (size_t)(row0 + m0 + mi*16 + g);
        size_t r2 = r1 + 8;
#pragma unroll
        for (int ni = 0; ni < 8; ni++) {
            int cc = col0 + n0 + ni*8 + 2*t;
            float b0 = 0.f, b1 = 0.f;
            if (bias) { b0 = bias[cc]; b1 = bias[cc + 1]; }
            float v0 = c[mi][ni][0] + b0, v1 = c[mi][ni][1] + b1;
            float v2 = c[mi][ni][2] + b0, v3 = c[mi][ni][3] + b1;
            if (TANH) { v0 = tanhf(v0); v1 = tanhf(v1); v2 = tanhf(v2); v3 = tanhf(v3); }
            if (PERMOUT) {
                int p0 = PERM(cc), p1 = PERM(cc + 1);
                C[r1*ldc + p0] = tfr(v0); C[r1*ldc + p1] = tfr(v1);
                C[r2*ldc + p0] = tfr(v2); C[r2*ldc + p1] = tfr(v3);
            } else {
                *(float2*)&C[r1*ldc + cc] = make_float2(v0, v1);
                *(float2*)&C[r2*ldc + cc] = make_float2(v2, v3);
            }
        }
    }
#undef LOADSTAGE
}

// ---------------- generic small SIMT GEMM (precompute path) ------------------
// OMODE via bools: TFPERM (tfr + PERM col), TFONLY (tfr, plain col)
template<bool TRANSA, bool TFPERM, bool TFONLY>
__global__ __launch_bounds__(256)
void sgemm_small(int M, int N, int K,
                 const float* __restrict__ A, int lda,
                 const float* __restrict__ B, int ldb,
                 float* __restrict__ C, int ldc)
{
    __shared__ float As[16][64];
    __shared__ float Bs[16][64];
    int tid = threadIdx.x;
    int m0 = blockIdx.y*64, n0 = blockIdx.x*64;
    int tx = tid & 15, ty = tid >> 4;
    float acc[4][4];
#pragma unroll
    for (int i = 0; i < 4; i++)
#pragma unroll
        for (int j = 0; j < 4; j++) acc[i][j] = 0.f;

    for (int k0 = 0; k0 < K; k0 += 16) {
        if (TRANSA) {
            for (int i = tid; i < 1024; i += 256) {
                int kk = i >> 6, mm = i & 63;
                As[kk][mm] = A[(size_t)(k0+kk)*lda + m0 + mm];
            }
        } else {
            for (int i = tid; i < 1024; i += 256) {
                int mm = i >> 4, kk = i & 15;
                As[kk][mm] = A[(size_t)(m0+mm)*lda + k0 + kk];
            }
        }
        for (int i = tid; i < 1024; i += 256) {
            int kk = i >> 6, nn = i & 63;
            Bs[kk][nn] = B[(size_t)(k0+kk)*ldb + n0 + nn];
        }
        __syncthreads();
#pragma unroll
        for (int kk = 0; kk < 16; kk++) {
            float4 a4 = *(const float4*)&As[kk][ty*4];
            float4 b4 = *(const float4*)&Bs[kk][tx*4];
            float a[4] = {a4.x, a4.y, a4.z, a4.w};
            float b[4] = {b4.x, b4.y, b4.z, b4.w};
#pragma unroll
            for (int i = 0; i < 4; i++)
#pragma unroll
                for (int j = 0; j < 4; j++)
                    acc[i][j] = fmaf(a[i], b[j], acc[i][j]);
        }
        __syncthreads();
    }
#pragma unroll
    for (int i = 0; i < 4; i++) {
        size_t m = (size_t)(m0 + ty*4 + i);
#pragma unroll
        for (int j = 0; j < 4; j++) {
            int n = n0 + tx*4 + j;
            if (TFPERM)      C[m*ldc + PERM(n)] = tfr(acc[i][j]);
            else if (TFONLY) C[m*ldc + n]       = tfr(acc[i][j]);
            else             C[m*ldc + n]       = acc[i][j];
        }
    }
}

// ---------------- build full_vals, nb, last_event_feat (tf32 + PERM) -------
__global__ void build_kernel(const int* __restrict__ nids,
                             const int* __restrict__ hist_nids,
                             const int* __restrict__ aids,
                             const int* __restrict__ eids,
                             const float* __restrict__ hist_ts,
                             const int* __restrict__ dirs,
                             const float* __restrict__ node_feat,
                             const float* __restrict__ edge_feat,
                             const float* __restrict__ anony,
                             const float* __restrict__ tw,
                             const float* __restrict__ tb)
{
    int bl = blockIdx.x;            // b*HL + l
    int b  = bl / HL, l = bl % HL;
    int j  = threadIdx.x;           // 0..127
    int jp = PERM(j);
    int hn  = hist_nids[bl];
    int dir = dirs[bl];
    int nid = nids[b];
    int src = dir ? nid : hn;
    int dst = dir ? hn  : nid;
    float sv = tfr(node_feat[(size_t)src*NF + j]);
    float dv = tfr(node_feat[(size_t)dst*NF + j]);
    float av = tfr(anony[(size_t)aids[bl]*NF + j]);
    float ev = tfr(edge_feat[(size_t)eids[bl]*EF + j]);
    float dt = hist_ts[b*HL + HL-1] - hist_ts[bl];
    float tv = tfr(cosf(dt*tw[j] + tb[j]));

    float* fv = g_full + (size_t)bl*DM;
    if (l == HL-1) {
        float* lef = g_lef + (size_t)b*DIN;
        lef[jp] = sv; lef[NF+jp] = dv; lef[2*NF+jp] = av; lef[3*NF+jp] = ev;
        fv[jp] = 0.f; fv[NF+jp] = 0.f; fv[2*NF+jp] = 0.f; fv[3*NF+jp] = 0.f;
        fv[4*NF+jp] = tv;
    } else {
        fv[jp] = sv; fv[NF+jp] = dv; fv[2*NF+jp] = av; fv[3*NF+jp] = ev;
        fv[4*NF+jp] = tv;
    }
    float* nb = g_nb + (size_t)bl*384;
    nb[jp]        = tfr(node_feat[(size_t)hn*NF + j]);
    nb[NF + jp]   = ev;
    nb[2*NF + jp] = tv;
}

// ---------------- merged weight prep: gwih | gwhh2 | odewT ------------------
__global__ void wprep(const float* __restrict__ gih,
                      const float* __restrict__ ghh,
                      const float* __restrict__ ow)
{
    int i = blockIdx.x*256 + threadIdx.x;
    if (i < 384*512) {
        int r = i / 512, c = i % 512;
        g_gwih[(size_t)r*512 + PERM(c)] = tfr(gih[i]);
    } else if (i < 384*512 + 384*128) {
        int k = i - 384*512;
        int r = k >> 7, c = k & 127;
        g_gwhh2[(size_t)r*128 + PERM(c)] = tfr(ghh[k]);
    } else if (i < 384*512 + 384*128 + 128*128) {
        int k = i - 384*512 - 384*128;
        int j = k >> 7, c = k & 127;
        g_odewT[c*NF + j] = ow[k];
    }
}

// Wcat[o, PERM(k)] = k<384 ? Wm2[k,o] : merge_w[(128 + k-384)*128 + o]
__global__ void wcat_build(const float* __restrict__ mw)
{
    int i = blockIdx.x*256 + threadIdx.x;   // 128*512
    if (i >= 128*512) return;
    int o = i >> 9, k = i & 511;
    float v = (k < 384) ? g_wm2[(size_t)k*128 + o]
                        : mw[(size_t)(128 + k - 384)*128 + o];
    g_wcat[(size_t)o*512 + PERM(k)] = tfr(v);
}

// ---------------- reductions ------------------------------------------------
__device__ __forceinline__ float block_reduce(float s)
{
    __shared__ float red[4];
    for (int o = 16; o; o >>= 1) s += __shfl_xor_sync(0xffffffffu, s, o);
    if ((threadIdx.x & 31) == 0) red[threadIdx.x >> 5] = s;
    __syncthreads();
    return red[0] + red[1] + red[2] + red[3];
}

// tqv[i] = ipb[i] + sum_j Wq[i, 512+j] * cos(tb[j])   (qlast vector)
__global__ void tqv_build(const float* __restrict__ ipw,
                          const float* __restrict__ ipb,
                          const float* __restrict__ tb)
{
    int i = blockIdx.x;                 // grid 640
    int j = threadIdx.x;                // 128
    float s = ipw[(size_t)i*640 + 512 + j] * cosf(tb[j]);
    float tot = block_reduce(s);
    if (j == 0) g_tqv[i] = ipb[i] + tot;
}

// u1v[640h+d] = sum_i tqv[320h+i] * Wk[320h+i, d]
__global__ void u1v_build(const float* __restrict__ ipw)
{
    int n = blockIdx.x;                 // grid 1280
    int h = n / 640, d = n - h*640;
    float s = 0.f;
    for (int i = threadIdx.x; i < 320; i += 128)
        s += g_tqv[320*h + i] * ipw[(size_t)(640 + 320*h + i)*640 + d];
    float tot = block_reduce(s);
    if (threadIdx.x == 0) g_u1v[n] = tot;
}

__global__ void bq2_build(const float* __restrict__ opb,
                          const float* __restrict__ outfn_w,
                          const float* __restrict__ outfn_b)
{
    int i = blockIdx.x;                 // grid 128
    float s = 0.f;
    for (int k = threadIdx.x; k < 640; k += 128)
        s += opb[k] * outfn_w[(size_t)i*640 + k];
    float tot = block_reduce(s);
    if (threadIdx.x == 0) g_bq2[i] = outfn_b[i] + tot;
}

__global__ void b4_build(const float* __restrict__ awq, const float* __restrict__ ipb)
{
    int o = blockIdx.x;                 // grid 128
    int t = threadIdx.x;
    float s = g_bq2[t] * awq[(size_t)t*128 + o];
    for (int m = t; m < 640; m += 128)
        s += g_w3[(size_t)o*640 + m] * ipb[1280 + m];
    float tot = block_reduce(s);
    if (threadIdx.x == 0) g_b4[o] = tot;
}

// b5[n] = sum_c awk[n,c] * b4[c]
__global__ void b5_build(const float* __restrict__ awk)
{
    int n = blockIdx.x;                 // grid 384
    int t = threadIdx.x;                // 128
    float s = awk[(size_t)n*128 + t] * g_b4[t];
    float tot = block_reduce(s);
    if (t == 0) g_b5[n] = tot;
}

// ---------------- attention 1: f cached in smem, constant u1 ----------------
__global__ __launch_bounds__(256)
void attn1_kernel(const int* __restrict__ hist_nids)
{
    extern __shared__ float asm1[];     // sf[12800] + su[1280] + sS[40] + sA[40]
    float* sf = asm1;
    float* su = asm1 + HL*DM;
    float* sS = su + 1280;
    float* sA = sS + 40;
    int b = blockIdx.x, tid = threadIdx.x;

    {   // load f tile (PERM space) once, coalesced
        const float4* src = (const float4*)(g_full + (size_t)b*HL*DM);
        float4* dst = (float4*)sf;
        for (int i = tid; i < HL*DM/4; i += 256) dst[i] = src[i];
        for (int x = tid; x < 1280; x += 256)
            su[x] = g_u1v[PERM(x)];      // batch-independent, L2-resident
    }
    __syncthreads();

    int warp = tid >> 5, lane = tid & 31;
    for (int m = warp; m < HL; m += 8) {
        const float* frow = sf + m*DM;
        float s0 = 0.f, s1 = 0.f;
#pragma unroll
        for (int i = 0; i < 20; i++) {
            int d = lane + i*32;
            float f = frow[d];
            s0 += su[d]*f; s1 += su[DM + d]*f;
        }
#pragma unroll
        for (int o = 16; o; o >>= 1) {
            s0 += __shfl_xor_sync(0xffffffffu, s0, o);
            s1 += __shfl_xor_sync(0xffffffffu, s1, o);
        }
        if (!lane) {
            sS[m]      = s0 * 0.05590169943749474f;   // 1/sqrt(320)
            sS[HL + m] = s1 * 0.05590169943749474f;
        }
    }
    __syncthreads();
    if (tid < NHEAD) {
        int h = tid;
        float sc[HL], mx = -1e30f;
        for (int m = 0; m < HL; m++) {
            float v = sS[h*HL + m];
            if (hist_nids[b*HL + m] == 0 && m != HL-1) v = -1e9f;
            sc[m] = v; mx = fmaxf(mx, v);
        }
        float sum = 0.f;
        for (int m = 0; m < HL; m++) { float e = expf(sc[m]-mx); sc[m] = e; sum += e; }
        float inv = 1.f/sum;
        for (int m = 0; m < HL; m++) sA[h*HL + m] = sc[m]*inv;
    }
    __syncthreads();
    for (int e = tid; e < DM; e += 256) {
        float a0 = 0.f, a1 = 0.f;
#pragma unroll
        for (int m = 0; m < HL; m++) {
            float f = sf[m*DM + e];
            a0 += sA[m]*f; a1 += sA[HL + m]*f;
        }
        g_s[(size_t)b*1280 + e]      = tfr(a0);
        g_s[(size_t)b*1280 + DM + e] = tfr(a1);
    }
}

// ---------------- attention 2: scores + weighted sums -> cat2 ---------------
__global__ __launch_bounds__(128)
void attn2_kernel(const int* __restrict__ nids,
                  const int* __restrict__ hist_nids,
                  const float* __restrict__ node_feat)
{
    __shared__ float snb[HL*384];       // 30KB: nb tile cached
    __shared__ float su2[384], sS[HL], sA[HL];
    int b = blockIdx.x, tid = threadIdx.x;
    {
        const float4* src = (const float4*)(g_nb + (size_t)b*HL*384);
        float4* dst = (float4*)snb;
        for (int i = tid; i < HL*384/4; i += 128) dst[i] = src[i];
#pragma unroll
        for (int q = 0; q < 3; q++)
            su2[tid + q*128] = g_u2[(size_t)b*384 + tid + q*128];
    }
    float nf = tfr(node_feat[(size_t)nids[b]*NF + tid]);
    __syncthreads();

    int warp = tid >> 5, lane = tid & 31;
    for (int l = warp; l < HL; l += 4) {
        const float* nr = snb + l*384;
        float s = 0.f;
#pragma unroll
        for (int i = 0; i < 12; i++) { int d = lane + i*32; s += su2[d]*nr[d]; }
#pragma unroll
        for (int o = 16; o; o >>= 1) s += __shfl_xor_sync(0xffffffffu, s, o);
        if (!lane) sS[l] = s * 0.08838834764831845f;  // 1/sqrt(128)
    }
    __syncthreads();
    if (tid == 0) {
        float sc[HL], mx = -1e30f;
        for (int l = 0; l < HL; l++) {
            float v = sS[l];
            if (hist_nids[b*HL + l] == 0 && l != HL-1) v = -1e9f;
            sc[l] = v; mx = fmaxf(mx, v);
        }
        float sum = 0.f;
        for (int l = 0; l < HL; l++) { float e = expf(sc[l]-mx); sc[l] = e; sum += e; }
        float inv = 1.f/sum;
        for (int l = 0; l < HL; l++) sA[l] = sc[l]*inv;
    }
    __syncthreads();
    float* cat = g_cat2 + (size_t)b*512;
#pragma unroll
    for (int q = 0; q < 3; q++) {
        int x = tid + q*128;               // PERM-space index into snb
        float acc = 0.f;
#pragma unroll
        for (int l = 0; l < HL; l++) acc += sA[l] * snb[l*384 + x];
        cat[x] = tfr(acc);                 // already PERM space
    }
    cat[384 + PERM(tid)] = nf;
}

// ---------------- ODE (RK4) + fused GRU elementwise, 8 samples/block --------
__global__ __launch_bounds__(128)
void ode_kernel(const float* __restrict__ hist_ts,
                const float* __restrict__ tnw,
                const float* __restrict__ tnb,
                const float* __restrict__ odeb,
                float* __restrict__ out)
{
    extern __shared__ float sm[];           // wsm[16384] + ysm[128*8]
    float* wsm = sm;
    float* ysm = sm + NF*NF;
    int j = threadIdx.x;
    int b0 = blockIdx.x * 8;

    for (int i = j; i < NF*NF; i += 128) wsm[i] = g_odewT[i];
    float tw = tnw[j], tb = tnb[j], ob = odeb[j];
    int jp = PERM(j);
    float t0v[8], rat[8], z[8];
#pragma unroll
    for (int s = 0; s < 8; s++) {
        int b = b0 + s;
        float a = hist_ts[b*HL + HL-2];
        float bb = hist_ts[b*HL + HL-1];
        t0v[s] = a; rat[s] = bb - a;
        const float* gi = g_gi + (size_t)b*384;
        const float* gh = g_gh + (size_t)b*384;
        float hpl = g_hpl[(size_t)b*NF + jp];
        float r  = 1.f/(1.f + expf(-(gi[j]        + gh[j])));
        float zg = 1.f/(1.f + expf(-(gi[NF + j]   + gh[NF + j])));
        float n  = tanhf(gi[2*NF + j] + r*gh[2*NF + j]);
        float hpr = (1.f - zg)*n + zg*hpl;
        z[s] = hpr;
        out[(size_t)BS*NF + (size_t)b*NF + j] = hpr;   // h_right
    }
    if (j < 8) out[(size_t)2*BS*NF + b0 + j] = hist_ts[(b0+j)*HL + HL-1];
    __syncthreads();
    const float ds = 1.f/ODE_STEPS;

    auto fstage = [&](float sfrac, const float* zi, float* f) {
        __syncthreads();
#pragma unroll
        for (int s = 0; s < 8; s++) {
            float te = __cosf((sfrac*rat[s] + t0v[s])*tw + tb);
            ysm[j*8 + s] = zi[s] + te;
        }
        __syncthreads();
        float acc[8];
#pragma unroll
        for (int s = 0; s < 8; s++) acc[s] = ob;
#pragma unroll 4
        for (int k = 0; k < NF; k++) {
            float w = wsm[k*NF + j];
            float4 y0 = *(const float4*)&ysm[k*8];
            float4 y1 = *(const float4*)&ysm[k*8 + 4];
            acc[0] = fmaf(y0.x, w, acc[0]);
            acc[1] = fmaf(y0.y, w, acc[1]);
            acc[2] = fmaf(y0.z, w, acc[2]);
            acc[3] = fmaf(y0.w, w, acc[3]);
            acc[4] = fmaf(y1.x, w, acc[4]);
            acc[5] = fmaf(y1.y, w, acc[5]);
            acc[6] = fmaf(y1.z, w, acc[6]);
            acc[7] = fmaf(y1.w, w, acc[7]);
        }
#pragma unroll
        for (int s = 0; s < 8; s++) {
            float th;
            asm("tanh.approx.f32 %0, %1;" : "=f"(th) : "f"(acc[s]));
            f[s] = th * rat[s];
        }
    };

    for (int i = 0; i < ODE_STEPS; i++) {
        float s0 = i * ds;
        float k1[8], k2[8], k3[8], k4[8], zi[8];
        fstage(s0, z, k1);
#pragma unroll
        for (int s = 0; s < 8; s++) zi[s] = z[s] + 0.5f*ds*k1[s];
        fstage(s0 + 0.5f*ds, zi, k2);
#pragma unroll
        for (int s = 0; s < 8; s++) zi[s] = z[s] + 0.5f*ds*k2[s];
        fstage(s0 + 0.5f*ds, zi, k3);
#pragma unroll
        for (int s = 0; s < 8; s++) zi[s] = z[s] + ds*k3[s];
        fstage(s0 + ds, zi, k4);
#pragma unroll
        for (int s = 0; s < 8; s++)
            z[s] += ds/6.f * (k1[s] + 2.f*k2[s] + 2.f*k3[s] + k4[s]);
    }
#pragma unroll
    for (int s = 0; s < 8; s++)
        out[(size_t)(b0+s)*NF + j] = z[s];   // h_left
}

// ---------------- host ------------------------------------------------------
extern "C" void kernel_launch(void* const* d_in, const int* in_sizes, int n_in,
                              void* d_out, int out_size)
{
    const int*   nids       = (const int*)  d_in[0];
    const int*   hist_nids  = (const int*)  d_in[2];
    const int*   aids       = (const int*)  d_in[3];
    const int*   eids       = (const int*)  d_in[4];
    const float* hist_ts    = (const float*)d_in[5];
    const int*   dirs       = (const int*)  d_in[6];
    const float* node_feat  = (const float*)d_in[7];
    const float* edge_feat  = (const float*)d_in[8];
    const float* anony_emb  = (const float*)d_in[9];
    const float* time_w     = (const float*)d_in[10];
    const float* time_b     = (const float*)d_in[11];
    const float* in_proj_w  = (const float*)d_in[12];
    const float* in_proj_b  = (const float*)d_in[13];
    const float* out_proj_w = (const float*)d_in[14];
    const float* out_proj_b = (const float*)d_in[15];
    const float* outfn_w    = (const float*)d_in[16];
    const float* outfn_b    = (const float*)d_in[17];
    const float* attn_wq    = (const float*)d_in[18];
    const float* attn_wk    = (const float*)d_in[19];
    const float* attn_wv    = (const float*)d_in[20];
    const float* merge_w    = (const float*)d_in[21];
    const float* merge_b    = (const float*)d_in[22];
    const float* gru_w_ih   = (const float*)d_in[23];
    const float* gru_w_hh   = (const float*)d_in[24];
    const float* gru_b_ih   = (const float*)d_in[25];
    const float* gru_b_hh   = (const float*)d_in[26];
    const float* ode_w      = (const float*)d_in[27];
    const float* ode_b      = (const float*)d_in[28];
    const float* tnode_w    = (const float*)d_in[29];
    const float* tnode_b    = (const float*)d_in[30];

    float* out = (float*)d_out;

    float *p_lef, *p_s, *p_u2, *p_gi, *p_cat2, *p_hpl,
          *p_gh, *p_gwih, *p_gwhh2, *p_wq2, *p_w3, *p_w4, *p_b4,
          *p_w5, *p_b5, *p_wm2, *p_wcat;
    cudaGetSymbolAddress((void**)&p_lef,   g_lef);
    cudaGetSymbolAddress((void**)&p_s,     g_s);
    cudaGetSymbolAddress((void**)&p_u2,    g_u2);
    cudaGetSymbolAddress((void**)&p_gi,    g_gi);
    cudaGetSymbolAddress((void**)&p_cat2,  g_cat2);
    cudaGetSymbolAddress((void**)&p_hpl,   g_hpl);
    cudaGetSymbolAddress((void**)&p_gh,    g_gh);
    cudaGetSymbolAddress((void**)&p_gwih,  g_gwih);
    cudaGetSymbolAddress((void**)&p_gwhh2, g_gwhh2);
    cudaGetSymbolAddress((void**)&p_wq2,   g_wq2);
    cudaGetSymbolAddress((void**)&p_w3,    g_w3);
    cudaGetSymbolAddress((void**)&p_w4,    g_w4);
    cudaGetSymbolAddress((void**)&p_b4,    g_b4);
    cudaGetSymbolAddress((void**)&p_w5,    g_w5);
    cudaGetSymbolAddress((void**)&p_b5,    g_b5);
    cudaGetSymbolAddress((void**)&p_wm2,   g_wm2);
    cudaGetSymbolAddress((void**)&p_wcat,  g_wcat);

    static bool init_done = false;
    static cudaStream_t s1;
    static cudaEvent_t e0, eu1, eall;
    if (!init_done) {
        cudaStreamCreateWithFlags(&s1, cudaStreamNonBlocking);
        cudaEventCreateWithFlags(&e0,   cudaEventDisableTiming);
        cudaEventCreateWithFlags(&eu1,  cudaEventDisableTiming);
        cudaEventCreateWithFlags(&eall, cudaEventDisableTiming);
        cudaFuncSetAttribute(ode_kernel, cudaFuncAttributeMaxDynamicSharedMemorySize,
                             (NF*NF + NF*8) * 4);
        cudaFuncSetAttribute(attn1_kernel, cudaFuncAttributeMaxDynamicSharedMemorySize,
                             (HL*DM + 1280 + 80) * 4);
        init_done = true;
    }

    // ---- fork: precompute chain on s1, wide gather on main stream ----
    cudaEventRecord(e0, 0);
    cudaStreamWaitEvent(s1, e0, 0);

    // s1 branch A: u1 vector first (attn1's only precompute dependency)
    tqv_build<<<640, 128, 0, s1>>>(in_proj_w, in_proj_b, time_b);
    u1v_build<<<1280, 128, 0, s1>>>(in_proj_w);
    cudaEventRecord(eu1, s1);

    // s1 branch B: remaining weight precompute
    wprep<<<(384*512 + 384*128 + 128*128 + 255)/256, 256, 0, s1>>>(
        gru_w_ih, gru_w_hh, ode_w);
    sgemm_small<false, false, false><<<dim3(10, 2), 256, 0, s1>>>(
        128, 640, 640, outfn_w, 640, out_proj_w, 640, p_wq2, 640);
    sgemm_small<true, false, false><<<dim3(10, 2), 256, 0, s1>>>(
        128, 640, 128, attn_wq, 128, p_wq2, 640, p_w3, 640);
    for (int h = 0; h < 2; h++)
        sgemm_small<false, true, false><<<dim3(10, 2), 256, 0, s1>>>(
            128, 640, 320,
            p_w3 + 320*h, 640,
            in_proj_w + (size_t)(1280 + 320*h)*640, 640,
            p_w4 + 640*h, 1280);
    // W5 = awk(NN) . W4  [384,1280], tf32, cols already PERM
    sgemm_small<false, false, true><<<dim3(20, 6), 256, 0, s1>>>(
        384, 1280, 128, attn_wk, 128, p_w4, 1280, p_w5, 1280);
    bq2_build<<<128, 128, 0, s1>>>(out_proj_b, outfn_w, outfn_b);
    b4_build<<<128, 128, 0, s1>>>(attn_wq, in_proj_b);
    b5_build<<<384, 128, 0, s1>>>(attn_wk);
    sgemm_small<false, false, false><<<dim3(2, 6), 256, 0, s1>>>(
        384, 128, 128, attn_wv, 128, merge_w, 128, p_wm2, 128);
    wcat_build<<<(128*512 + 255)/256, 256, 0, s1>>>(merge_w);
    cudaEventRecord(eall, s1);

    // main stream: wide gather (overlaps s1)
    build_kernel<<<BS*HL, 128>>>(nids, hist_nids, aids, eids, hist_ts, dirs,
                                 node_feat, edge_feat, anony_emb, time_w, time_b);

    // join 1: u1v ready -> attention 1
    cudaStreamWaitEvent(0, eu1, 0);
    attn1_kernel<<<BS, 256, (HL*DM + 1280 + 80)*4>>>(hist_nids);

    // join 2: all weights ready
    cudaStreamWaitEvent(0, eall, 0);

    // gi = lef @ gru_w_ih^T
    tgemm<false,false><<<dim3(3, 32), 256>>>(DIN, p_lef, DIN, p_gwih, p_gi,
                                             384, gru_b_ih);

    // u2 = s @ W5^T + b5  (qh folded in; PERM out)
    tgemm<true,false><<<dim3(3, 32), 256>>>(1280, p_s, 1280, p_w5, p_u2, 384,
                                            p_b5);

    // attention 2 -> cat2
    attn2_kernel<<<BS, 128>>>(nids, hist_nids, node_feat);

    // hpl = tanh(cat2 @ Wcat^T + merge_b) (PERM out)
    tgemm<true,true><<<dim3(1, 32), 256>>>(512, p_cat2, 512, p_wcat, p_hpl,
                                           NF, merge_b);

    // gh = hpl @ gru_w_hh^T + b_hh
    tgemm<false,false><<<dim3(3, 32), 256>>>(NF, p_hpl, NF, p_gwhh2, p_gh,
                                             384, gru_b_hh);

    // ODE RK4 + fused GRU (writes h_left, h_right, ts)
    ode_kernel<<<BS/8, 128, (NF*NF + NF*8)*4>>>(hist_ts, tnode_w, tnode_b,
                                                ode_b, out);
}

// round 17
// speedup vs baseline: 1.4311x; 1.4311x over previous
#include <cuda_runtime.h>
#include <cuda_bf16.h>
#include <math.h>
#include <stdint.h>

// Problem constants
#define BS 4096
#define HL 20
#define NF 128
#define EF 128
#define TF 128
#define DM 640          // 3*NF + EF + TF
#define DIN 512         // DM - TF
#define NHEAD 2
#define DH 320          // DM / NHEAD
#define ODE_STEPS 8

// K-block interleave (4x4 transpose within each 16-block; self-inverse).
#define PERM(k) (((k) & ~15) | (((k) & 3) << 2) | (((k) & 15) >> 2))

// ---------------- scratch (device globals; no allocation allowed) ----------
__device__ float g_full [(size_t)BS*HL*DM];     // full_vals (tf32, PERM space)
__device__ float g_nb   [(size_t)BS*HL*384];    // nb (tf32, PERM space)
__device__ float g_lef  [(size_t)BS*DIN];       // last_event_feat (tf32, PERM)
__device__ float g_u1v  [1280];                 // batch-independent u1 vector
__device__ float g_tqv  [640];                  // qlast vector (batch-indep)
__device__ float g_s    [(size_t)BS*1280];      // weighted sums (tf32, PERM)
__device__ float g_u2   [(size_t)BS*384];       // u2 (tf32, PERM)
__device__ float g_gi   [(size_t)BS*384];
__device__ float g_cat2 [(size_t)BS*512];       // [ss2|nf] (tf32, PERM)
__device__ float g_hpl  [(size_t)BS*NF];        // tanh-merge out (tf32, PERM)
__device__ float g_gh   [(size_t)BS*384];       // GRU hh gates (normal)
__device__ float g_odewT[NF*NF];
__device__ float g_gwih [384*512];              // tf32+PERM gru_w_ih
__device__ float g_gwhh2[384*128];              // tf32+PERM gru_w_hh
__device__ float g_wq2  [128*640];              // outfn_w @ out_proj_w (fp32)
__device__ float g_w3   [128*640];              // attn_wq^T outfn out_proj (fp32)
__device__ float g_bq2  [128];
__device__ float g_w4   [128*1280];             // W3 folded with Wv (tf32, K-PERM)
__device__ float g_b4   [128];
__device__ float g_w5   [384*1280];             // awk . W4 (tf32, K-PERM)
__device__ float g_b5   [384];                  // awk . b4
__device__ float g_wm2  [384*128];              // attn_wv @ merge_w_top (fp32)
__device__ float g_wcat [128*512];              // [Wm2; merge_w_bot]^T (tf32, K-PERM)

__device__ __forceinline__ uint32_t f2tf(float x) {
    uint32_t u; asm("cvt.rna.tf32.f32 %0, %1;" : "=r"(u) : "f"(x)); return u;
}
__device__ __forceinline__ float tfr(float x) { return __uint_as_float(f2tf(x)); }

__device__ __forceinline__ void cp16(uint32_t dst, const void* src) {
    asm volatile("cp.async.cg.shared.global [%0], [%1], 16;" :: "r"(dst), "l"(src));
}

// ---------------- TF32 mma.sync GEMM, TN form, K-interleaved operands -------
template<bool PERMOUT, bool TANH>
__global__ __launch_bounds__(256, 2)
void tgemm(int K, const float* __restrict__ A, int lda,
           const float* __restrict__ B,
           float* __restrict__ C, int ldc,
           const float* __restrict__ bias)
{
    __shared__ float As[3][128][16];
    __shared__ float Bs[3][128][16];
    int tid = threadIdx.x;
    int warp = tid >> 5, lane = tid & 31;
    int row0 = blockIdx.y * 128, col0 = blockIdx.x * 128;
    int m0 = (warp >> 1) * 32, n0 = (warp & 1) * 64;
    int g = lane >> 2, t = lane & 3;

    float c[2][8][4];
#pragma unroll
    for (int mi = 0; mi < 2; mi++)
#pragma unroll
        for (int ni = 0; ni < 8; ni++)
#pragma unroll
            for (int i = 0; i < 4; i++) c[mi][ni][i] = 0.f;

    const float* Ap = A + (size_t)row0 * lda;
    const float* Bp = B + (size_t)col0 * K;

    uint32_t sA = (uint32_t)__cvta_generic_to_shared(&As[0][0][0]);
    uint32_t sB = (uint32_t)__cvta_generic_to_shared(&Bs[0][0][0]);
    const uint32_t stg = 128u*16u*4u;

#define LOADSTAGE(s, kt) {                                                    \
        _Pragma("unroll")                                                     \
        for (int i = 0; i < 2; i++) {                                         \
            int j = tid + i*256, r = j >> 2, q = j & 3;                       \
            cp16(sA + (uint32_t)(s)*stg + (uint32_t)(r*16 + q*4)*4u,          \
                 Ap + (size_t)r*lda + (kt)*16 + q*4);                         \
            cp16(sB + (uint32_t)(s)*stg + (uint32_t)(r*16 + q*4)*4u,          \
                 Bp + (size_t)r*K + (kt)*16 + q*4);                           \
        }                                                                     \
        asm volatile("cp.async.commit_group;" ::: "memory");                  \
    }

    int T = K >> 4;
    LOADSTAGE(0, 0);
    LOADSTAGE(1, 1);

    int s = 0, sw = 2;
    for (int kt = 0; kt < T; kt++) {
        if (kt + 1 < T) asm volatile("cp.async.wait_group 1;" ::: "memory");
        else            asm volatile("cp.async.wait_group 0;" ::: "memory");
        __syncthreads();
        if (kt + 2 < T) LOADSTAGE(sw, kt + 2);

        float4 av[2][2], bv[8];
#pragma unroll
        for (int mi = 0; mi < 2; mi++) {
            int rm = m0 + mi*16 + g;
            av[mi][0] = *(const float4*)&As[s][rm    ][t*4];
            av[mi][1] = *(const float4*)&As[s][rm + 8][t*4];
        }
#pragma unroll
        for (int ni = 0; ni < 8; ni++) {
            int cn = n0 + ni*8 + g;
            bv[ni] = *(const float4*)&Bs[s][cn][t*4];
        }
#pragma unroll
        for (int mi = 0; mi < 2; mi++)
#pragma unroll
            for (int ni = 0; ni < 8; ni++) {
                asm volatile(
                    "mma.sync.aligned.m16n8k8.row.col.f32.tf32.tf32.f32 "
                    "{%0,%1,%2,%3},{%4,%5,%6,%7},{%8,%9},{%0,%1,%2,%3};\n"
                    : "+f"(c[mi][ni][0]), "+f"(c[mi][ni][1]),
                      "+f"(c[mi][ni][2]), "+f"(c[mi][ni][3])
                    : "r"(__float_as_uint(av[mi][0].x)), "r"(__float_as_uint(av[mi][1].x)),
                      "r"(__float_as_uint(av[mi][0].y)), "r"(__float_as_uint(av[mi][1].y)),
                      "r"(__float_as_uint(bv[ni].x)),    "r"(__float_as_uint(bv[ni].y)));
                asm volatile(
                    "mma.sync.aligned.m16n8k8.row.col.f32.tf32.tf32.f32 "
                    "{%0,%1,%2,%3},{%4,%5,%6,%7},{%8,%9},{%0,%1,%2,%3};\n"
                    : "+f"(c[mi][ni][0]), "+f"(c[mi][ni][1]),
                      "+f"(c[mi][ni][2]), "+f"(c[mi][ni][3])
                    : "r"(__float_as_uint(av[mi][0].z)), "r"(__float_as_uint(av[mi][1].z)),
                      "r"(__float_as_uint(av[mi][0].w)), "r"(__float_as_uint(av[mi][1].w)),
                      "r"(__float_as_uint(bv[ni].z)),    "r"(__float_as_uint(bv[ni].w)));
            }
        __syncthreads();
        s  = (s  == 2) ? 0 : s  + 1;
        sw = (sw == 2) ? 0 : sw + 1;
    }

#pragma unroll
    for (int mi = 0; mi < 2; mi++) {
        size_t r1 = (size_t)(row0 + m0 + mi*16 + g);
        size_t r2 = r1 + 8;
#pragma unroll
        for (int ni = 0; ni < 8; ni++) {
            int cc = col0 + n0 + ni*8 + 2*t;
            float b0 = 0.f, b1 = 0.f;
            if (bias) { b0 = bias[cc]; b1 = bias[cc + 1]; }
            float v0 = c[mi][ni][0] + b0, v1 = c[mi][ni][1] + b1;
            float v2 = c[mi][ni][2] + b0, v3 = c[mi][ni][3] + b1;
            if (TANH) { v0 = tanhf(v0); v1 = tanhf(v1); v2 = tanhf(v2); v3 = tanhf(v3); }
            if (PERMOUT) {
                int p0 = PERM(cc), p1 = PERM(cc + 1);
                C[r1*ldc + p0] = tfr(v0); C[r1*ldc + p1] = tfr(v1);
                C[r2*ldc + p0] = tfr(v2); C[r2*ldc + p1] = tfr(v3);
            } else {
                *(float2*)&C[r1*ldc + cc] = make_float2(v0, v1);
                *(float2*)&C[r2*ldc + cc] = make_float2(v2, v3);
            }
        }
    }
#undef LOADSTAGE
}

// ---------------- small SIMT GEMM, 2-stage pipelined (precompute path) ------
// OMODE via bools: TFPERM (tfr + PERM col), TFONLY (tfr, plain col)
template<bool TRANSA, bool TFPERM, bool TFONLY>
__global__ __launch_bounds__(256)
void sgemm_small(int M, int N, int K,
                 const float* __restrict__ A, int lda,
                 const float* __restrict__ B, int ldb,
                 float* __restrict__ C, int ldc)
{
    __shared__ float As[2][16][68];     // padded rows: conflict-light stores
    __shared__ float Bs[2][16][64];
    int tid = threadIdx.x;
    int m0 = blockIdx.y*64, n0 = blockIdx.x*64;
    int tx = tid & 15, ty = tid >> 4;
    float acc[4][4];
#pragma unroll
    for (int i = 0; i < 4; i++)
#pragma unroll
        for (int j = 0; j < 4; j++) acc[i][j] = 0.f;

    uint32_t sB = (uint32_t)__cvta_generic_to_shared(&Bs[0][0][0]);
    float ra[4];

#define REGLOADA(k0) {                                                        \
        _Pragma("unroll")                                                     \
        for (int i = 0; i < 4; i++) {                                         \
            int e = tid + i*256;                                              \
            if (TRANSA) { int kk = e>>6, mm = e&63;                           \
                ra[i] = A[(size_t)((k0)+kk)*lda + m0 + mm]; }                 \
            else        { int kk = e&15, mm = e>>4;                           \
                ra[i] = A[(size_t)(m0+mm)*lda + (k0) + kk]; }                 \
        }                                                                     \
    }
#define REGSTOREA(s) {                                                        \
        _Pragma("unroll")                                                     \
        for (int i = 0; i < 4; i++) {                                         \
            int e = tid + i*256;                                              \
            int kk = TRANSA ? (e>>6) : (e&15);                                \
            int mm = TRANSA ? (e&63) : (e>>4);                                \
            As[s][kk][mm] = ra[i];                                            \
        }                                                                     \
    }
#define LOADB(s, k0) {                                                        \
        int kk = tid >> 4, nn4 = (tid & 15)*4;                                \
        cp16(sB + (uint32_t)(s)*16u*64u*4u + (uint32_t)(kk*64 + nn4)*4u,      \
             B + (size_t)((k0)+kk)*ldb + n0 + nn4);                           \
        asm volatile("cp.async.commit_group;" ::: "memory");                  \
    }

    int T = K >> 4;
    REGLOADA(0); REGSTOREA(0);
    LOADB(0, 0);

    for (int kt = 0; kt < T; kt++) {
        int s = kt & 1;
        asm volatile("cp.async.wait_group 0;" ::: "memory");
        __syncthreads();
        if (kt + 1 < T) { LOADB(s^1, (kt+1)*16); REGLOADA((kt+1)*16); }
#pragma unroll
        for (int kk = 0; kk < 16; kk++) {
            float4 a4 = *(const float4*)&As[s][kk][ty*4];
            float4 b4 = *(const float4*)&Bs[s][kk][tx*4];
            float a[4] = {a4.x, a4.y, a4.z, a4.w};
            float b[4] = {b4.x, b4.y, b4.z, b4.w};
#pragma unroll
            for (int i = 0; i < 4; i++)
#pragma unroll
                for (int j = 0; j < 4; j++)
                    acc[i][j] = fmaf(a[i], b[j], acc[i][j]);
        }
        if (kt + 1 < T) REGSTOREA(s^1);
    }
#pragma unroll
    for (int i = 0; i < 4; i++) {
        size_t m = (size_t)(m0 + ty*4 + i);
#pragma unroll
        for (int j = 0; j < 4; j++) {
            int n = n0 + tx*4 + j;
            if (TFPERM)      C[m*ldc + PERM(n)] = tfr(acc[i][j]);
            else if (TFONLY) C[m*ldc + n]       = tfr(acc[i][j]);
            else             C[m*ldc + n]       = acc[i][j];
        }
    }
#undef REGLOADA
#undef REGSTOREA
#undef LOADB
}

// ---------------- build full_vals, nb, last_event_feat (tf32 + PERM) -------
__global__ void build_kernel(const int* __restrict__ nids,
                             const int* __restrict__ hist_nids,
                             const int* __restrict__ aids,
                             const int* __restrict__ eids,
                             const float* __restrict__ hist_ts,
                             const int* __restrict__ dirs,
                             const float* __restrict__ node_feat,
                             const float* __restrict__ edge_feat,
                             const float* __restrict__ anony,
                             const float* __restrict__ tw,
                             const float* __restrict__ tb)
{
    int bl = blockIdx.x;            // b*HL + l
    int b  = bl / HL, l = bl % HL;
    int j  = threadIdx.x;           // 0..127
    int jp = PERM(j);
    int hn  = hist_nids[bl];
    int dir = dirs[bl];
    int nid = nids[b];
    int src = dir ? nid : hn;
    int dst = dir ? hn  : nid;
    float sv = tfr(node_feat[(size_t)src*NF + j]);
    float dv = tfr(node_feat[(size_t)dst*NF + j]);
    float av = tfr(anony[(size_t)aids[bl]*NF + j]);
    float ev = tfr(edge_feat[(size_t)eids[bl]*EF + j]);
    float dt = hist_ts[b*HL + HL-1] - hist_ts[bl];
    float tv = tfr(cosf(dt*tw[j] + tb[j]));

    float* fv = g_full + (size_t)bl*DM;
    if (l == HL-1) {
        float* lef = g_lef + (size_t)b*DIN;
        lef[jp] = sv; lef[NF+jp] = dv; lef[2*NF+jp] = av; lef[3*NF+jp] = ev;
        fv[jp] = 0.f; fv[NF+jp] = 0.f; fv[2*NF+jp] = 0.f; fv[3*NF+jp] = 0.f;
        fv[4*NF+jp] = tv;
    } else {
        fv[jp] = sv; fv[NF+jp] = dv; fv[2*NF+jp] = av; fv[3*NF+jp] = ev;
        fv[4*NF+jp] = tv;
    }
    float* nb = g_nb + (size_t)bl*384;
    nb[jp]        = tfr(node_feat[(size_t)hn*NF + j]);
    nb[NF + jp]   = ev;
    nb[2*NF + jp] = tv;
}

// ---------------- merged weight prep: gwih | gwhh2 | odewT ------------------
__global__ void wprep(const float* __restrict__ gih,
                      const float* __restrict__ ghh,
                      const float* __restrict__ ow)
{
    int i = blockIdx.x*256 + threadIdx.x;
    if (i < 384*512) {
        int r = i / 512, c = i % 512;
        g_gwih[(size_t)r*512 + PERM(c)] = tfr(gih[i]);
    } else if (i < 384*512 + 384*128) {
        int k = i - 384*512;
        int r = k >> 7, c = k & 127;
        g_gwhh2[(size_t)r*128 + PERM(c)] = tfr(ghh[k]);
    } else if (i < 384*512 + 384*128 + 128*128) {
        int k = i - 384*512 - 384*128;
        int j = k >> 7, c = k & 127;
        g_odewT[c*NF + j] = ow[k];
    }
}

// Wcat[o, PERM(k)] = k<384 ? Wm2[k,o] : merge_w[(128 + k-384)*128 + o]
__global__ void wcat_build(const float* __restrict__ mw)
{
    int i = blockIdx.x*256 + threadIdx.x;   // 128*512
    if (i >= 128*512) return;
    int o = i >> 9, k = i & 511;
    float v = (k < 384) ? g_wm2[(size_t)k*128 + o]
                        : mw[(size_t)(128 + k - 384)*128 + o];
    g_wcat[(size_t)o*512 + PERM(k)] = tfr(v);
}

// ---------------- reductions ------------------------------------------------
__device__ __forceinline__ float block_reduce(float s)
{
    __shared__ float red[4];
    for (int o = 16; o; o >>= 1) s += __shfl_xor_sync(0xffffffffu, s, o);
    if ((threadIdx.x & 31) == 0) red[threadIdx.x >> 5] = s;
    __syncthreads();
    return red[0] + red[1] + red[2] + red[3];
}

// tqv[i] = ipb[i] + sum_j Wq[i, 512+j] * cos(tb[j])   (qlast vector)
__global__ void tqv_build(const float* __restrict__ ipw,
                          const float* __restrict__ ipb,
                          const float* __restrict__ tb)
{
    int i = blockIdx.x;                 // grid 640
    int j = threadIdx.x;                // 128
    float s = ipw[(size_t)i*640 + 512 + j] * cosf(tb[j]);
    float tot = block_reduce(s);
    if (j == 0) g_tqv[i] = ipb[i] + tot;
}

// u1v[640h+d] = sum_i tqv[320h+i] * Wk[320h+i, d]
__global__ void u1v_build(const float* __restrict__ ipw)
{
    int n = blockIdx.x;                 // grid 1280
    int h = n / 640, d = n - h*640;
    float s = 0.f;
    for (int i = threadIdx.x; i < 320; i += 128)
        s += g_tqv[320*h + i] * ipw[(size_t)(640 + 320*h + i)*640 + d];
    float tot = block_reduce(s);
    if (threadIdx.x == 0) g_u1v[n] = tot;
}

__global__ void bq2_build(const float* __restrict__ opb,
                          const float* __restrict__ outfn_w,
                          const float* __restrict__ outfn_b)
{
    int i = blockIdx.x;                 // grid 128
    float s = 0.f;
    for (int k = threadIdx.x; k < 640; k += 128)
        s += opb[k] * outfn_w[(size_t)i*640 + k];
    float tot = block_reduce(s);
    if (threadIdx.x == 0) g_bq2[i] = outfn_b[i] + tot;
}

__global__ void b4_build(const float* __restrict__ awq, const float* __restrict__ ipb)
{
    int o = blockIdx.x;                 // grid 128
    int t = threadIdx.x;
    float s = g_bq2[t] * awq[(size_t)t*128 + o];
    for (int m = t; m < 640; m += 128)
        s += g_w3[(size_t)o*640 + m] * ipb[1280 + m];
    float tot = block_reduce(s);
    if (threadIdx.x == 0) g_b4[o] = tot;
}

// b5[n] = sum_c awk[n,c] * b4[c]
__global__ void b5_build(const float* __restrict__ awk)
{
    int n = blockIdx.x;                 // grid 384
    int t = threadIdx.x;                // 128
    float s = awk[(size_t)n*128 + t] * g_b4[t];
    float tot = block_reduce(s);
    if (t == 0) g_b5[n] = tot;
}

// ---------------- attention 1: f cached in smem, constant u1 ----------------
__global__ __launch_bounds__(256)
void attn1_kernel(const int* __restrict__ hist_nids)
{
    extern __shared__ float asm1[];     // sf[12800] + su[1280] + sS[40] + sA[40]
    float* sf = asm1;
    float* su = asm1 + HL*DM;
    float* sS = su + 1280;
    float* sA = sS + 40;
    int b = blockIdx.x, tid = threadIdx.x;

    {   // load f tile (PERM space) once, coalesced
        const float4* src = (const float4*)(g_full + (size_t)b*HL*DM);
        float4* dst = (float4*)sf;
        for (int i = tid; i < HL*DM/4; i += 256) dst[i] = src[i];
        for (int x = tid; x < 1280; x += 256)
            su[x] = g_u1v[PERM(x)];      // batch-independent, L2-resident
    }
    __syncthreads();

    int warp = tid >> 5, lane = tid & 31;
    for (int m = warp; m < HL; m += 8) {
        const float* frow = sf + m*DM;
        float s0 = 0.f, s1 = 0.f;
#pragma unroll
        for (int i = 0; i < 20; i++) {
            int d = lane + i*32;
            float f = frow[d];
            s0 += su[d]*f; s1 += su[DM + d]*f;
        }
#pragma unroll
        for (int o = 16; o; o >>= 1) {
            s0 += __shfl_xor_sync(0xffffffffu, s0, o);
            s1 += __shfl_xor_sync(0xffffffffu, s1, o);
        }
        if (!lane) {
            sS[m]      = s0 * 0.05590169943749474f;   // 1/sqrt(320)
            sS[HL + m] = s1 * 0.05590169943749474f;
        }
    }
    __syncthreads();
    if (tid < NHEAD) {
        int h = tid;
        float sc[HL], mx = -1e30f;
        for (int m = 0; m < HL; m++) {
            float v = sS[h*HL + m];
            if (hist_nids[b*HL + m] == 0 && m != HL-1) v = -1e9f;
            sc[m] = v; mx = fmaxf(mx, v);
        }
        float sum = 0.f;
        for (int m = 0; m < HL; m++) { float e = expf(sc[m]-mx); sc[m] = e; sum += e; }
        float inv = 1.f/sum;
        for (int m = 0; m < HL; m++) sA[h*HL + m] = sc[m]*inv;
    }
    __syncthreads();
    for (int e = tid; e < DM; e += 256) {
        float a0 = 0.f, a1 = 0.f;
#pragma unroll
        for (int m = 0; m < HL; m++) {
            float f = sf[m*DM + e];
            a0 += sA[m]*f; a1 += sA[HL + m]*f;
        }
        g_s[(size_t)b*1280 + e]      = tfr(a0);
        g_s[(size_t)b*1280 + DM + e] = tfr(a1);
    }
}

// ---------------- attention 2: scores + weighted sums -> cat2 ---------------
__global__ __launch_bounds__(128)
void attn2_kernel(const int* __restrict__ nids,
                  const int* __restrict__ hist_nids,
                  const float* __restrict__ node_feat)
{
    __shared__ float snb[HL*384];       // 30KB: nb tile cached
    __shared__ float su2[384], sS[HL], sA[HL];
    int b = blockIdx.x, tid = threadIdx.x;
    {
        const float4* src = (const float4*)(g_nb + (size_t)b*HL*384);
        float4* dst = (float4*)snb;
        for (int i = tid; i < HL*384/4; i += 128) dst[i] = src[i];
#pragma unroll
        for (int q = 0; q < 3; q++)
            su2[tid + q*128] = g_u2[(size_t)b*384 + tid + q*128];
    }
    float nf = tfr(node_feat[(size_t)nids[b]*NF + tid]);
    __syncthreads();

    int warp = tid >> 5, lane = tid & 31;
    for (int l = warp; l < HL; l += 4) {
        const float* nr = snb + l*384;
        float s = 0.f;
#pragma unroll
        for (int i = 0; i < 12; i++) { int d = lane + i*32; s += su2[d]*nr[d]; }
#pragma unroll
        for (int o = 16; o; o >>= 1) s += __shfl_xor_sync(0xffffffffu, s, o);
        if (!lane) sS[l] = s * 0.08838834764831845f;  // 1/sqrt(128)
    }
    __syncthreads();
    if (tid == 0) {
        float sc[HL], mx = -1e30f;
        for (int l = 0; l < HL; l++) {
            float v = sS[l];
            if (hist_nids[b*HL + l] == 0 && l != HL-1) v = -1e9f;
            sc[l] = v; mx = fmaxf(mx, v);
        }
        float sum = 0.f;
        for (int l = 0; l < HL; l++) { float e = expf(sc[l]-mx); sc[l] = e; sum += e; }
        float inv = 1.f/sum;
        for (int l = 0; l < HL; l++) sA[l] = sc[l]*inv;
    }
    __syncthreads();
    float* cat = g_cat2 + (size_t)b*512;
#pragma unroll
    for (int q = 0; q < 3; q++) {
        int x = tid + q*128;               // PERM-space index into snb
        float acc = 0.f;
#pragma unroll
        for (int l = 0; l < HL; l++) acc += sA[l] * snb[l*384 + x];
        cat[x] = tfr(acc);                 // already PERM space
    }
    cat[384 + PERM(tid)] = nf;
}

// ---------------- ODE (RK4) + fused GRU elementwise, 8 samples/block --------
__global__ __launch_bounds__(128)
void ode_kernel(const float* __restrict__ hist_ts,
                const float* __restrict__ tnw,
                const float* __restrict__ tnb,
                const float* __restrict__ odeb,
                float* __restrict__ out)
{
    extern __shared__ float sm[];           // wsm[16384] + ysm[128*8]
    float* wsm = sm;
    float* ysm = sm + NF*NF;
    int j = threadIdx.x;
    int b0 = blockIdx.x * 8;

    for (int i = j; i < NF*NF; i += 128) wsm[i] = g_odewT[i];
    float tw = tnw[j], tb = tnb[j], ob = odeb[j];
    int jp = PERM(j);
    float t0v[8], rat[8], z[8];
#pragma unroll
    for (int s = 0; s < 8; s++) {
        int b = b0 + s;
        float a = hist_ts[b*HL + HL-2];
        float bb = hist_ts[b*HL + HL-1];
        t0v[s] = a; rat[s] = bb - a;
        const float* gi = g_gi + (size_t)b*384;
        const float* gh = g_gh + (size_t)b*384;
        float hpl = g_hpl[(size_t)b*NF + jp];
        float r  = 1.f/(1.f + expf(-(gi[j]        + gh[j])));
        float zg = 1.f/(1.f + expf(-(gi[NF + j]   + gh[NF + j])));
        float n  = tanhf(gi[2*NF + j] + r*gh[2*NF + j]);
        float hpr = (1.f - zg)*n + zg*hpl;
        z[s] = hpr;
        out[(size_t)BS*NF + (size_t)b*NF + j] = hpr;   // h_right
    }
    if (j < 8) out[(size_t)2*BS*NF + b0 + j] = hist_ts[(b0+j)*HL + HL-1];
    __syncthreads();
    const float ds = 1.f/ODE_STEPS;

    auto fstage = [&](float sfrac, const float* zi, float* f) {
        __syncthreads();
#pragma unroll
        for (int s = 0; s < 8; s++) {
            float te = __cosf((sfrac*rat[s] + t0v[s])*tw + tb);
            ysm[j*8 + s] = zi[s] + te;
        }
        __syncthreads();
        float acc[8];
#pragma unroll
        for (int s = 0; s < 8; s++) acc[s] = ob;
#pragma unroll 4
        for (int k = 0; k < NF; k++) {
            float w = wsm[k*NF + j];
            float4 y0 = *(const float4*)&ysm[k*8];
            float4 y1 = *(const float4*)&ysm[k*8 + 4];
            acc[0] = fmaf(y0.x, w, acc[0]);
            acc[1] = fmaf(y0.y, w, acc[1]);
            acc[2] = fmaf(y0.z, w, acc[2]);
            acc[3] = fmaf(y0.w, w, acc[3]);
            acc[4] = fmaf(y1.x, w, acc[4]);
            acc[5] = fmaf(y1.y, w, acc[5]);
            acc[6] = fmaf(y1.z, w, acc[6]);
            acc[7] = fmaf(y1.w, w, acc[7]);
        }
#pragma unroll
        for (int s = 0; s < 8; s++) {
            float th;
            asm("tanh.approx.f32 %0, %1;" : "=f"(th) : "f"(acc[s]));
            f[s] = th * rat[s];
        }
    };

    for (int i = 0; i < ODE_STEPS; i++) {
        float s0 = i * ds;
        float k1[8], k2[8], k3[8], k4[8], zi[8];
        fstage(s0, z, k1);
#pragma unroll
        for (int s = 0; s < 8; s++) zi[s] = z[s] + 0.5f*ds*k1[s];
        fstage(s0 + 0.5f*ds, zi, k2);
#pragma unroll
        for (int s = 0; s < 8; s++) zi[s] = z[s] + 0.5f*ds*k2[s];
        fstage(s0 + 0.5f*ds, zi, k3);
#pragma unroll
        for (int s = 0; s < 8; s++) zi[s] = z[s] + ds*k3[s];
        fstage(s0 + ds, zi, k4);
#pragma unroll
        for (int s = 0; s < 8; s++)
            z[s] += ds/6.f * (k1[s] + 2.f*k2[s] + 2.f*k3[s] + k4[s]);
    }
#pragma unroll
    for (int s = 0; s < 8; s++)
        out[(size_t)(b0+s)*NF + j] = z[s];   // h_left
}

// ---------------- host ------------------------------------------------------
extern "C" void kernel_launch(void* const* d_in, const int* in_sizes, int n_in,
                              void* d_out, int out_size)
{
    const int*   nids       = (const int*)  d_in[0];
    const int*   hist_nids  = (const int*)  d_in[2];
    const int*   aids       = (const int*)  d_in[3];
    const int*   eids       = (const int*)  d_in[4];
    const float* hist_ts    = (const float*)d_in[5];
    const int*   dirs       = (const int*)  d_in[6];
    const float* node_feat  = (const float*)d_in[7];
    const float* edge_feat  = (const float*)d_in[8];
    const float* anony_emb  = (const float*)d_in[9];
    const float* time_w     = (const float*)d_in[10];
    const float* time_b     = (const float*)d_in[11];
    const float* in_proj_w  = (const float*)d_in[12];
    const float* in_proj_b  = (const float*)d_in[13];
    const float* out_proj_w = (const float*)d_in[14];
    const float* out_proj_b = (const float*)d_in[15];
    const float* outfn_w    = (const float*)d_in[16];
    const float* outfn_b    = (const float*)d_in[17];
    const float* attn_wq    = (const float*)d_in[18];
    const float* attn_wk    = (const float*)d_in[19];
    const float* attn_wv    = (const float*)d_in[20];
    const float* merge_w    = (const float*)d_in[21];
    const float* merge_b    = (const float*)d_in[22];
    const float* gru_w_ih   = (const float*)d_in[23];
    const float* gru_w_hh   = (const float*)d_in[24];
    const float* gru_b_ih   = (const float*)d_in[25];
    const float* gru_b_hh   = (const float*)d_in[26];
    const float* ode_w      = (const float*)d_in[27];
    const float* ode_b      = (const float*)d_in[28];
    const float* tnode_w    = (const float*)d_in[29];
    const float* tnode_b    = (const float*)d_in[30];

    float* out = (float*)d_out;

    float *p_lef, *p_s, *p_u2, *p_gi, *p_cat2, *p_hpl,
          *p_gh, *p_gwih, *p_gwhh2, *p_wq2, *p_w3, *p_w4, *p_b4,
          *p_w5, *p_b5, *p_wm2, *p_wcat;
    cudaGetSymbolAddress((void**)&p_lef,   g_lef);
    cudaGetSymbolAddress((void**)&p_s,     g_s);
    cudaGetSymbolAddress((void**)&p_u2,    g_u2);
    cudaGetSymbolAddress((void**)&p_gi,    g_gi);
    cudaGetSymbolAddress((void**)&p_cat2,  g_cat2);
    cudaGetSymbolAddress((void**)&p_hpl,   g_hpl);
    cudaGetSymbolAddress((void**)&p_gh,    g_gh);
    cudaGetSymbolAddress((void**)&p_gwih,  g_gwih);
    cudaGetSymbolAddress((void**)&p_gwhh2, g_gwhh2);
    cudaGetSymbolAddress((void**)&p_wq2,   g_wq2);
    cudaGetSymbolAddress((void**)&p_w3,    g_w3);
    cudaGetSymbolAddress((void**)&p_w4,    g_w4);
    cudaGetSymbolAddress((void**)&p_b4,    g_b4);
    cudaGetSymbolAddress((void**)&p_w5,    g_w5);
    cudaGetSymbolAddress((void**)&p_b5,    g_b5);
    cudaGetSymbolAddress((void**)&p_wm2,   g_wm2);
    cudaGetSymbolAddress((void**)&p_wcat,  g_wcat);

    static bool init_done = false;
    static cudaStream_t s1;
    static cudaEvent_t e0, eu1, eall;
    if (!init_done) {
        cudaStreamCreateWithFlags(&s1, cudaStreamNonBlocking);
        cudaEventCreateWithFlags(&e0,   cudaEventDisableTiming);
        cudaEventCreateWithFlags(&eu1,  cudaEventDisableTiming);
        cudaEventCreateWithFlags(&eall, cudaEventDisableTiming);
        cudaFuncSetAttribute(ode_kernel, cudaFuncAttributeMaxDynamicSharedMemorySize,
                             (NF*NF + NF*8) * 4);
        cudaFuncSetAttribute(attn1_kernel, cudaFuncAttributeMaxDynamicSharedMemorySize,
                             (HL*DM + 1280 + 80) * 4);
        init_done = true;
    }

    // ---- fork: precompute chain on s1, wide gather on main stream ----
    cudaEventRecord(e0, 0);
    cudaStreamWaitEvent(s1, e0, 0);

    // s1 branch A: u1 vector first (attn1's only precompute dependency)
    tqv_build<<<640, 128, 0, s1>>>(in_proj_w, in_proj_b, time_b);
    u1v_build<<<1280, 128, 0, s1>>>(in_proj_w);
    cudaEventRecord(eu1, s1);

    // s1 branch B: the long W-chain first (critical), leaves after
    sgemm_small<false, false, false><<<dim3(10, 2), 256, 0, s1>>>(
        128, 640, 640, outfn_w, 640, out_proj_w, 640, p_wq2, 640);
    sgemm_small<true, false, false><<<dim3(10, 2), 256, 0, s1>>>(
        128, 640, 128, attn_wq, 128, p_wq2, 640, p_w3, 640);
    for (int h = 0; h < 2; h++)
        sgemm_small<false, true, false><<<dim3(10, 2), 256, 0, s1>>>(
            128, 640, 320,
            p_w3 + 320*h, 640,
            in_proj_w + (size_t)(1280 + 320*h)*640, 640,
            p_w4 + 640*h, 1280);
    // W5 = awk(NN) . W4  [384,1280], tf32, cols already PERM
    sgemm_small<false, false, true><<<dim3(20, 6), 256, 0, s1>>>(
        384, 1280, 128, attn_wk, 128, p_w4, 1280, p_w5, 1280);
    bq2_build<<<128, 128, 0, s1>>>(out_proj_b, outfn_w, outfn_b);
    b4_build<<<128, 128, 0, s1>>>(attn_wq, in_proj_b);
    b5_build<<<384, 128, 0, s1>>>(attn_wk);
    sgemm_small<false, false, false><<<dim3(2, 6), 256, 0, s1>>>(
        384, 128, 128, attn_wv, 128, merge_w, 128, p_wm2, 128);
    wcat_build<<<(128*512 + 255)/256, 256, 0, s1>>>(merge_w);
    wprep<<<(384*512 + 384*128 + 128*128 + 255)/256, 256, 0, s1>>>(
        gru_w_ih, gru_w_hh, ode_w);
    cudaEventRecord(eall, s1);

    // main stream: wide gather (overlaps s1)
    build_kernel<<<BS*HL, 128>>>(nids, hist_nids, aids, eids, hist_ts, dirs,
                                 node_feat, edge_feat, anony_emb, time_w, time_b);

    // join 1: u1v ready -> attention 1
    cudaStreamWaitEvent(0, eu1, 0);
    attn1_kernel<<<BS, 256, (HL*DM + 1280 + 80)*4>>>(hist_nids);

    // join 2: all weights ready
    cudaStreamWaitEvent(0, eall, 0);

    // gi = lef @ gru_w_ih^T
    tgemm<false,false><<<dim3(3, 32), 256>>>(DIN, p_lef, DIN, p_gwih, p_gi,
                                             384, gru_b_ih);

    // u2 = s @ W5^T + b5  (qh folded in; PERM out)
    tgemm<true,false><<<dim3(3, 32), 256>>>(1280, p_s, 1280, p_w5, p_u2, 384,
                                            p_b5);

    // attention 2 -> cat2
    attn2_kernel<<<BS, 128>>>(nids, hist_nids, node_feat);

    // hpl = tanh(cat2 @ Wcat^T + merge_b) (PERM out)
    tgemm<true,true><<<dim3(1, 32), 256>>>(512, p_cat2, 512, p_wcat, p_hpl,
                                           NF, merge_b);

    // gh = hpl @ gru_w_hh^T + b_hh
    tgemm<false,false><<<dim3(3, 32), 256>>>(NF, p_hpl, NF, p_gwhh2, p_gh,
                                             384, gru_b_hh);

    // ODE RK4 + fused GRU (writes h_left, h_right, ts)
    ode_kernel<<<BS/8, 128, (NF*NF + NF*8)*4>>>(hist_ts, tnode_w, tnode_b,
                                                ode_b, out);
}